// round 1
// baseline (speedup 1.0000x reference)
#include <cuda_runtime.h>
#include <cuda_bf16.h>
#include <cstdint>

// Problem constants
#define BATCH   262144
#define IN_DIM  256
#define HID     128
#define OUT_DIM 15
#define NCAM    15

#define NHB     512           // histogram blocks (BATCH/512 elems each)
#define ELEMS_PER_HB (BATCH / NHB)   // 512
#define MAX_TILES 2080        // >= ceil(B/128) + NCAM = 2063

// ---------------- device scratch (no allocations allowed) ----------------
__device__ int g_blockcnt[NHB * NCAM];   // per-block per-camera counts -> bases
__device__ int g_perm[BATCH];            // rows sorted by camera
__device__ int g_off[NCAM + 1];          // camera segment offsets
__device__ int g_tile_cam[MAX_TILES];
__device__ int g_tile_row[MAX_TILES];
__device__ int g_ntiles;

// ---------------- helpers ----------------
__device__ __forceinline__ uint32_t f2tf32(float f) {
    uint32_t u;
    asm("cvt.rna.tf32.f32 %0, %1;" : "=r"(u) : "f"(f));
    return u;
}

__device__ __forceinline__ void mma_tf32(float* d, const uint32_t* a, const uint32_t* b) {
    asm volatile(
        "mma.sync.aligned.m16n8k8.row.col.f32.tf32.tf32.f32 "
        "{%0,%1,%2,%3}, {%4,%5,%6,%7}, {%8,%9}, {%0,%1,%2,%3};"
        : "+f"(d[0]), "+f"(d[1]), "+f"(d[2]), "+f"(d[3])
        : "r"(a[0]), "r"(a[1]), "r"(a[2]), "r"(a[3]), "r"(b[0]), "r"(b[1]));
}

// ---------------- kernel 1: per-block histogram ----------------
__global__ __launch_bounds__(256) void hist_kernel(const int* __restrict__ cam) {
    __shared__ int s_cnt[NCAM];
    int tid = threadIdx.x;
    if (tid < NCAM) s_cnt[tid] = 0;
    __syncthreads();
    int base = blockIdx.x * ELEMS_PER_HB;
#pragma unroll
    for (int j = 0; j < ELEMS_PER_HB / 256; j++) {
        int c = cam[base + j * 256 + tid];
        atomicAdd(&s_cnt[c], 1);
    }
    __syncthreads();
    if (tid < NCAM) g_blockcnt[blockIdx.x * NCAM + tid] = s_cnt[tid];
}

// ---------------- kernel 2: scan + tile table (1 block, 512 threads) ------
__global__ __launch_bounds__(512) void scan_kernel() {
    __shared__ int s[NHB];
    __shared__ int s_off[NCAM + 1];
    __shared__ int s_tp[NCAM + 1];
    int tid = threadIdx.x;
    int running = 0;
    for (int c = 0; c < NCAM; c++) {
        int v = g_blockcnt[tid * NCAM + c];
        s[tid] = v;
        __syncthreads();
#pragma unroll
        for (int d = 1; d < NHB; d <<= 1) {
            int t = (tid >= d) ? s[tid - d] : 0;
            __syncthreads();
            s[tid] += t;
            __syncthreads();
        }
        int incl = s[tid];
        int tot = s[NHB - 1];
        g_blockcnt[tid * NCAM + c] = running + incl - v;  // exclusive base for this block
        if (tid == 0) { s_off[c] = running; g_off[c] = running; }
        running += tot;
        __syncthreads();
    }
    if (tid == 0) { s_off[NCAM] = running; g_off[NCAM] = running; }
    __syncthreads();

    if (tid == 0) {
        int acc = 0;
        for (int c = 0; c < NCAM; c++) {
            s_tp[c] = acc;
            int cnt = s_off[c + 1] - s_off[c];
            acc += (cnt + 127) >> 7;
        }
        s_tp[NCAM] = acc;
        g_ntiles = acc;
    }
    __syncthreads();
    int nt = s_tp[NCAM];
    for (int t = tid; t < nt; t += NHB) {
        int c = 0;
        while (c < NCAM - 1 && t >= s_tp[c + 1]) c++;
        g_tile_cam[t] = c;
        g_tile_row[t] = s_off[c] + ((t - s_tp[c]) << 7);
    }
}

// ---------------- kernel 3: scatter permutation ----------------
__global__ __launch_bounds__(256) void scatter_kernel(const int* __restrict__ cam) {
    __shared__ int s_cur[NCAM];
    int tid = threadIdx.x;
    if (tid < NCAM) s_cur[tid] = g_blockcnt[blockIdx.x * NCAM + tid];
    __syncthreads();
    int base = blockIdx.x * ELEMS_PER_HB;
#pragma unroll
    for (int j = 0; j < ELEMS_PER_HB / 256; j++) {
        int i = base + j * 256 + tid;
        int c = cam[i];
        int pos = atomicAdd(&s_cur[c], 1);
        g_perm[pos] = i;
    }
}

// ---------------- kernel 4: grouped 2-layer MLP (M=128 tiles) -------------
// smem layouts (padded for conflict-free tf32 fragment reads):
//   A   : [128 rows][36]  (bank = 4r+c, distinct over a warp)
//   W1  : [32 k   ][136]  (bank = 8k+n, distinct; conflict-free staging)
//   H   : [128 rows][68]  (layer-2 A operand, one 64-col half at a time)
//   W2  : [64 k   ][24]
#define SA_STRIDE 36
#define SW1_STRIDE 136
#define SH_STRIDE 68
#define SW2_STRIDE 24
#define UNION_FLOATS (128 * SA_STRIDE + 32 * SW1_STRIDE)   // 8960 > 128*68=8704

__global__ __launch_bounds__(256) void mlp_kernel(
    const float* __restrict__ x,
    const float* __restrict__ W1,
    const float* __restrict__ b1,
    const float* __restrict__ W2,
    const float* __restrict__ b2,
    float* __restrict__ out)
{
    int t = blockIdx.x;
    if (t >= g_ntiles) return;

    __shared__ float s_buf[UNION_FLOATS];
    __shared__ float s_w2[64 * SW2_STRIDE];
    __shared__ int   s_perm[128];
    __shared__ float s_b1[HID];
    __shared__ float s_b2[OUT_DIM];

    float* S_A  = s_buf;                       // [128][36]
    float* S_W1 = s_buf + 128 * SA_STRIDE;     // [32][136]
    float* S_H  = s_buf;                       // [128][68]  (reuses A+W1 region)

    int c    = g_tile_cam[t];
    int row0 = g_tile_row[t];
    int nrows = g_off[c + 1] - row0;
    if (nrows > 128) nrows = 128;

    int tid  = threadIdx.x;
    int warp = tid >> 5;
    int lane = tid & 31;
    int wm = warp >> 1;     // 0..3  (m 32-row block)
    int wn = warp & 1;      // 0..1  (n 64-col half)
    int gq = lane >> 2;     // groupID (0..7)
    int tg = lane & 3;      // threadID_in_group (0..3)

    if (tid < 128) {
        s_perm[tid] = (tid < nrows) ? g_perm[row0 + tid] : g_perm[row0];
        s_b1[tid]   = b1[c * HID + tid];
    }
    if (tid < OUT_DIM) s_b2[tid] = b2[c * OUT_DIM + tid];
    __syncthreads();

    float acc[2][8][4];
#pragma unroll
    for (int mt = 0; mt < 2; mt++)
#pragma unroll
        for (int nt = 0; nt < 8; nt++)
#pragma unroll
            for (int e = 0; e < 4; e++) acc[mt][nt][e] = 0.f;

    const float* W1c = W1 + (size_t)c * IN_DIM * HID;

    // ---- mainloop over K = 256 in chunks of 32 ----
    for (int kc = 0; kc < IN_DIM / 32; kc++) {
        // stage A: 128 rows x 32 k (gathered via perm), converted to tf32
        {
            int rsub = tid >> 3;        // 0..31
            int c4   = tid & 7;         // 0..7 float4s
#pragma unroll
            for (int i = 0; i < 4; i++) {
                int row = i * 32 + rsub;
                int g = s_perm[row];
                const float4 v = *(const float4*)(x + (size_t)g * IN_DIM + kc * 32 + c4 * 4);
                uint4 w;
                w.x = f2tf32(v.x); w.y = f2tf32(v.y); w.z = f2tf32(v.z); w.w = f2tf32(v.w);
                *(uint4*)(S_A + row * SA_STRIDE + c4 * 4) = w;
            }
        }
        // stage W1 chunk: 32 k-rows x 128 n (natural layout), converted to tf32
        {
#pragma unroll
            for (int i = 0; i < 4; i++) {
                int f4 = i * 256 + tid;     // 0..1023
                int k  = f4 >> 5;           // 0..31
                int n4 = f4 & 31;           // 0..31 float4s
                const float4 v = *(const float4*)(W1c + (size_t)(kc * 32 + k) * HID + n4 * 4);
                uint4 w;
                w.x = f2tf32(v.x); w.y = f2tf32(v.y); w.z = f2tf32(v.z); w.w = f2tf32(v.w);
                *(uint4*)(S_W1 + k * SW1_STRIDE + n4 * 4) = w;
            }
        }
        __syncthreads();

#pragma unroll
        for (int kk = 0; kk < 4; kk++) {
            uint32_t af[2][4];
            int ccol = kk * 8 + tg;
#pragma unroll
            for (int mt = 0; mt < 2; mt++) {
                int rbase = (wm * 32 + mt * 16 + gq) * SA_STRIDE + ccol;
                af[mt][0] = __float_as_uint(S_A[rbase]);
                af[mt][1] = __float_as_uint(S_A[rbase + 8 * SA_STRIDE]);
                af[mt][2] = __float_as_uint(S_A[rbase + 4]);
                af[mt][3] = __float_as_uint(S_A[rbase + 8 * SA_STRIDE + 4]);
            }
#pragma unroll
            for (int nt = 0; nt < 8; nt++) {
                uint32_t bf[2];
                int n  = wn * 64 + nt * 8 + gq;
                int kb = kk * 8 + tg;
                bf[0] = __float_as_uint(S_W1[kb * SW1_STRIDE + n]);
                bf[1] = __float_as_uint(S_W1[(kb + 4) * SW1_STRIDE + n]);
#pragma unroll
                for (int mt = 0; mt < 2; mt++) mma_tf32(acc[mt][nt], af[mt], bf);
            }
        }
        __syncthreads();
    }

    // ---- layer 2: out = relu(h+b1) @ W2 + b2, via two 64-col halves ----
    float acc2[2][4];
#pragma unroll
    for (int nt = 0; nt < 2; nt++)
#pragma unroll
        for (int e = 0; e < 4; e++) acc2[nt][e] = 0.f;

    for (int half = 0; half < 2; half++) {
        __syncthreads();  // protect S_H vs prior reads (mainloop / previous half mma)
        if (wn == half) {
            // stage relu(acc + b1) -> S_H (local cols 0..63), tf32
#pragma unroll
            for (int mt = 0; mt < 2; mt++) {
#pragma unroll
                for (int nt = 0; nt < 8; nt++) {
                    int r    = wm * 32 + mt * 16 + gq;
                    int colb = nt * 8 + 2 * tg;
                    int gc   = half * 64 + colb;
                    float v0 = fmaxf(acc[mt][nt][0] + s_b1[gc],     0.f);
                    float v1 = fmaxf(acc[mt][nt][1] + s_b1[gc + 1], 0.f);
                    float v2 = fmaxf(acc[mt][nt][2] + s_b1[gc],     0.f);
                    float v3 = fmaxf(acc[mt][nt][3] + s_b1[gc + 1], 0.f);
                    S_H[r * SH_STRIDE + colb]           = __uint_as_float(f2tf32(v0));
                    S_H[r * SH_STRIDE + colb + 1]       = __uint_as_float(f2tf32(v1));
                    S_H[(r + 8) * SH_STRIDE + colb]     = __uint_as_float(f2tf32(v2));
                    S_H[(r + 8) * SH_STRIDE + colb + 1] = __uint_as_float(f2tf32(v3));
                }
            }
        }
        // stage W2 half: k = half*64 .. +63, n padded to 16
        for (int idx = tid; idx < 64 * 16; idx += 256) {
            int k = idx >> 4;
            int n = idx & 15;
            float v = (n < OUT_DIM) ? W2[((size_t)c * HID + half * 64 + k) * OUT_DIM + n] : 0.f;
            s_w2[k * SW2_STRIDE + n] = __uint_as_float(f2tf32(v));
        }
        __syncthreads();

        int r0 = warp * 16 + gq;   // warp = mtile index (8 warps, 8 m16 tiles)
#pragma unroll
        for (int kk = 0; kk < 8; kk++) {
            uint32_t af[4];
            int base = r0 * SH_STRIDE + kk * 8 + tg;
            af[0] = __float_as_uint(S_H[base]);
            af[1] = __float_as_uint(S_H[base + 8 * SH_STRIDE]);
            af[2] = __float_as_uint(S_H[base + 4]);
            af[3] = __float_as_uint(S_H[base + 8 * SH_STRIDE + 4]);
            int kb = kk * 8 + tg;
#pragma unroll
            for (int nt = 0; nt < 2; nt++) {
                uint32_t bf[2];
                bf[0] = __float_as_uint(s_w2[kb * SW2_STRIDE + nt * 8 + gq]);
                bf[1] = __float_as_uint(s_w2[(kb + 4) * SW2_STRIDE + nt * 8 + gq]);
                mma_tf32(acc2[nt], af, bf);
            }
        }
    }

    // ---- store: out[perm[row]][col] = acc2 + b2 ----
#pragma unroll
    for (int nt = 0; nt < 2; nt++) {
#pragma unroll
        for (int e = 0; e < 4; e++) {
            int row = warp * 16 + gq + (e >> 1) * 8;
            int col = nt * 8 + 2 * tg + (e & 1);
            if (row < nrows && col < OUT_DIM) {
                int g = s_perm[row];
                out[(size_t)g * OUT_DIM + col] = acc2[nt][e] + s_b2[col];
            }
        }
    }
}

// ---------------- launch ----------------
extern "C" void kernel_launch(void* const* d_in, const int* in_sizes, int n_in,
                              void* d_out, int out_size) {
    const float* x   = (const float*)d_in[0];
    const int*   cam = (const int*)d_in[1];
    const float* W1  = (const float*)d_in[2];
    const float* b1  = (const float*)d_in[3];
    const float* W2  = (const float*)d_in[4];
    const float* b2  = (const float*)d_in[5];
    float* out = (float*)d_out;

    hist_kernel<<<NHB, 256>>>(cam);
    scan_kernel<<<1, NHB>>>();
    scatter_kernel<<<NHB, 256>>>(cam);
    mlp_kernel<<<MAX_TILES, 256>>>(x, W1, b1, W2, b2, out);
}

// round 3
// speedup vs baseline: 1.4124x; 1.4124x over previous
#include <cuda_runtime.h>
#include <cuda_bf16.h>
#include <cstdint>

// Problem constants
#define BATCH   262144
#define IN_DIM  256
#define HID     128
#define OUT_DIM 15
#define NCAM    15

#define NHB     512
#define ELEMS_PER_HB (BATCH / NHB)   // 512
#define MAX_TILES 2080               // >= ceil(B/128) + NCAM = 2063

// ---------------- device scratch ----------------
__device__ int g_blockcnt[NHB * NCAM];
__device__ int g_perm[BATCH];
__device__ int g_off[NCAM + 1];
__device__ int g_tile_cam[MAX_TILES];
__device__ int g_tile_row[MAX_TILES];
__device__ int g_ntiles;
__device__ float g_w1t[NCAM * IN_DIM * HID];      // W1 pre-rounded to tf32
__device__ float g_w2t[NCAM * HID * 16];          // W2 pre-rounded, n padded to 16

// ---------------- helpers ----------------
__device__ __forceinline__ uint32_t f2tf32(float f) {
    uint32_t u;
    asm("cvt.rna.tf32.f32 %0, %1;" : "=r"(u) : "f"(f));
    return u;
}

__device__ __forceinline__ void mma_tf32(float* d, const uint32_t* a, const uint32_t* b) {
    asm volatile(
        "mma.sync.aligned.m16n8k8.row.col.f32.tf32.tf32.f32 "
        "{%0,%1,%2,%3}, {%4,%5,%6,%7}, {%8,%9}, {%0,%1,%2,%3};"
        : "+f"(d[0]), "+f"(d[1]), "+f"(d[2]), "+f"(d[3])
        : "r"(a[0]), "r"(a[1]), "r"(a[2]), "r"(a[3]), "r"(b[0]), "r"(b[1]));
}

__device__ __forceinline__ void cp_async16(uint32_t smem_addr, const void* gptr) {
    asm volatile("cp.async.cg.shared.global [%0], [%1], 16;\n" :: "r"(smem_addr), "l"(gptr));
}
__device__ __forceinline__ void cp_commit() {
    asm volatile("cp.async.commit_group;\n");
}
template <int N>
__device__ __forceinline__ void cp_wait() {
    asm volatile("cp.async.wait_group %0;\n" :: "n"(N));
}

// ---------------- kernel 0: pre-round weights to tf32 ----------------
__global__ __launch_bounds__(256) void wconv_kernel(
    const float* __restrict__ W1, const float* __restrict__ W2)
{
    int n1 = NCAM * IN_DIM * HID;
    for (int i = blockIdx.x * 256 + threadIdx.x; i < n1; i += gridDim.x * 256)
        g_w1t[i] = __uint_as_float(f2tf32(W1[i]));
    int n2 = NCAM * HID * 16;
    for (int i = blockIdx.x * 256 + threadIdx.x; i < n2; i += gridDim.x * 256) {
        int n = i & 15;
        int ck = i >> 4;
        g_w2t[i] = (n < OUT_DIM) ? __uint_as_float(f2tf32(W2[ck * OUT_DIM + n])) : 0.f;
    }
}

// ---------------- kernel 1: per-block histogram ----------------
__global__ __launch_bounds__(256) void hist_kernel(const int* __restrict__ cam) {
    __shared__ int s_cnt[NCAM];
    int tid = threadIdx.x;
    if (tid < NCAM) s_cnt[tid] = 0;
    __syncthreads();
    int base = blockIdx.x * ELEMS_PER_HB;
#pragma unroll
    for (int j = 0; j < ELEMS_PER_HB / 256; j++) {
        int c = cam[base + j * 256 + tid];
        atomicAdd(&s_cnt[c], 1);
    }
    __syncthreads();
    if (tid < NCAM) g_blockcnt[blockIdx.x * NCAM + tid] = s_cnt[tid];
}

// ---------------- kernel 2: scan + tile table ----------------
__global__ __launch_bounds__(512) void scan_kernel() {
    __shared__ int s[NHB];
    __shared__ int s_off[NCAM + 1];
    __shared__ int s_tp[NCAM + 1];
    int tid = threadIdx.x;
    int running = 0;
    for (int c = 0; c < NCAM; c++) {
        int v = g_blockcnt[tid * NCAM + c];
        s[tid] = v;
        __syncthreads();
#pragma unroll
        for (int d = 1; d < NHB; d <<= 1) {
            int t = (tid >= d) ? s[tid - d] : 0;
            __syncthreads();
            s[tid] += t;
            __syncthreads();
        }
        int incl = s[tid];
        int tot = s[NHB - 1];
        g_blockcnt[tid * NCAM + c] = running + incl - v;
        if (tid == 0) { s_off[c] = running; g_off[c] = running; }
        running += tot;
        __syncthreads();
    }
    if (tid == 0) { s_off[NCAM] = running; g_off[NCAM] = running; }
    __syncthreads();

    if (tid == 0) {
        int acc = 0;
        for (int c = 0; c < NCAM; c++) {
            s_tp[c] = acc;
            int cnt = s_off[c + 1] - s_off[c];
            acc += (cnt + 127) >> 7;
        }
        s_tp[NCAM] = acc;
        g_ntiles = acc;
    }
    __syncthreads();
    int nt = s_tp[NCAM];
    for (int t = tid; t < nt; t += NHB) {
        int c = 0;
        while (c < NCAM - 1 && t >= s_tp[c + 1]) c++;
        g_tile_cam[t] = c;
        g_tile_row[t] = s_off[c] + ((t - s_tp[c]) << 7);
    }
}

// ---------------- kernel 3: scatter permutation ----------------
__global__ __launch_bounds__(256) void scatter_kernel(const int* __restrict__ cam) {
    __shared__ int s_cur[NCAM];
    int tid = threadIdx.x;
    if (tid < NCAM) s_cur[tid] = g_blockcnt[blockIdx.x * NCAM + tid];
    __syncthreads();
    int base = blockIdx.x * ELEMS_PER_HB;
#pragma unroll
    for (int j = 0; j < ELEMS_PER_HB / 256; j++) {
        int i = base + j * 256 + tid;
        int c = cam[i];
        int pos = atomicAdd(&s_cur[c], 1);
        g_perm[pos] = i;
    }
}

// ---------------- kernel 4: grouped 2-layer MLP, pipelined ----------------
// smem (dynamic) layout, in floats:
//   S_A  : [128][36]            @ 0          (4608)
//   S_W1 : 2 x [32][136]        @ 4608       (8704)  (cp.async ping/pong)
//   S_H  : [128][68]            overlaps S_W1 (8704)
//   s_w2 : [64][24]             @ 13312      (1536)
//   s_perm (int[128]), s_b1[128], s_b2[16]   @ 14848..15120
#define SA_STRIDE 36
#define SW1_STRIDE 136
#define SW1_BUF (32 * SW1_STRIDE)      // 4352
#define SH_STRIDE 68
#define SW2_STRIDE 24
#define SMEM_FLOATS 15120
#define SMEM_BYTES (SMEM_FLOATS * 4)

__global__ __launch_bounds__(256, 2) void mlp_kernel(
    const float* __restrict__ x,
    const float* __restrict__ b1,
    const float* __restrict__ b2,
    float* __restrict__ out)
{
    int t = blockIdx.x;
    if (t >= g_ntiles) return;

    extern __shared__ float smem[];
    float* S_A  = smem;
    float* S_W1 = smem + 4608;
    float* S_H  = S_W1;
    float* s_w2 = smem + 13312;
    int*   s_perm = (int*)(smem + 14848);
    float* s_b1 = smem + 14976;
    float* s_b2 = smem + 15104;

    int c    = g_tile_cam[t];
    int row0 = g_tile_row[t];
    int nrows = g_off[c + 1] - row0;
    if (nrows > 128) nrows = 128;

    int tid  = threadIdx.x;
    int warp = tid >> 5;
    int lane = tid & 31;
    int wm = warp >> 1;
    int wn = warp & 1;
    int gq = lane >> 2;
    int tg = lane & 3;

    if (tid < 128) {
        s_perm[tid] = (tid < nrows) ? g_perm[row0 + tid] : g_perm[row0];
        s_b1[tid]   = b1[c * HID + tid];
    }
    if (tid < OUT_DIM) s_b2[tid] = b2[c * OUT_DIM + tid];
    __syncthreads();

    // per-thread A staging geometry: 4 rows, 1 float4 each
    int rsub = tid >> 3;        // 0..31
    int c4   = tid & 7;         // 0..7
    const float* aptr[4];
#pragma unroll
    for (int i = 0; i < 4; i++) {
        int g = s_perm[i * 32 + rsub];
        aptr[i] = x + (size_t)g * IN_DIM + c4 * 4;
    }

    // W1 cp.async geometry: 4 float4 per thread per 32x128 chunk
    const float* W1c = g_w1t + (size_t)c * IN_DIM * HID;
    uint32_t sw1_base = (uint32_t)__cvta_generic_to_shared(S_W1);

    float acc[2][8][4];
#pragma unroll
    for (int mt = 0; mt < 2; mt++)
#pragma unroll
        for (int nt = 0; nt < 8; nt++)
#pragma unroll
            for (int e = 0; e < 4; e++) acc[mt][nt][e] = 0.f;

    // ---- prologue: W1 chunk0 via cp.async, A chunk0 into regs ----
#pragma unroll
    for (int i = 0; i < 4; i++) {
        int f4 = i * 256 + tid;
        int k  = f4 >> 5;
        int n4 = f4 & 31;
        cp_async16(sw1_base + (k * SW1_STRIDE + n4 * 4) * 4,
                   W1c + (size_t)k * HID + n4 * 4);
    }
    cp_commit();
    float4 a_regs[4];
#pragma unroll
    for (int i = 0; i < 4; i++) a_regs[i] = *(const float4*)(aptr[i]);

    // ---- mainloop: K = 256 in 8 chunks of 32 ----
    for (int kc = 0; kc < 8; kc++) {
        float* w1buf = S_W1 + (kc & 1) * SW1_BUF;

        // issue next W1 chunk
        if (kc < 7) {
            uint32_t dstb = sw1_base + ((kc + 1) & 1) * SW1_BUF * 4;
            const float* src = W1c + (size_t)(kc + 1) * 32 * HID;
#pragma unroll
            for (int i = 0; i < 4; i++) {
                int f4 = i * 256 + tid;
                int k  = f4 >> 5;
                int n4 = f4 & 31;
                cp_async16(dstb + (k * SW1_STRIDE + n4 * 4) * 4,
                           src + (size_t)k * HID + n4 * 4);
            }
            cp_commit();
        }

        // store A regs (cvt to tf32) into S_A
#pragma unroll
        for (int i = 0; i < 4; i++) {
            uint4 w;
            w.x = f2tf32(a_regs[i].x); w.y = f2tf32(a_regs[i].y);
            w.z = f2tf32(a_regs[i].z); w.w = f2tf32(a_regs[i].w);
            *(uint4*)(S_A + (i * 32 + rsub) * SA_STRIDE + c4 * 4) = w;
        }

        if (kc < 7) cp_wait<1>(); else cp_wait<0>();
        __syncthreads();

        // issue next A gather loads (consumed next iteration)
        if (kc < 7) {
#pragma unroll
            for (int i = 0; i < 4; i++)
                a_regs[i] = *(const float4*)(aptr[i] + (kc + 1) * 32);
        }

        // MMA phase on S_A x w1buf
#pragma unroll
        for (int kk = 0; kk < 4; kk++) {
            uint32_t af[2][4];
            int ccol = kk * 8 + tg;
#pragma unroll
            for (int mt = 0; mt < 2; mt++) {
                int rbase = (wm * 32 + mt * 16 + gq) * SA_STRIDE + ccol;
                af[mt][0] = __float_as_uint(S_A[rbase]);
                af[mt][1] = __float_as_uint(S_A[rbase + 8 * SA_STRIDE]);
                af[mt][2] = __float_as_uint(S_A[rbase + 4]);
                af[mt][3] = __float_as_uint(S_A[rbase + 8 * SA_STRIDE + 4]);
            }
#pragma unroll
            for (int nt = 0; nt < 8; nt++) {
                uint32_t bf[2];
                int n  = wn * 64 + nt * 8 + gq;
                int kb = kk * 8 + tg;
                bf[0] = __float_as_uint(w1buf[kb * SW1_STRIDE + n]);
                bf[1] = __float_as_uint(w1buf[(kb + 4) * SW1_STRIDE + n]);
#pragma unroll
                for (int mt = 0; mt < 2; mt++) mma_tf32(acc[mt][nt], af[mt], bf);
            }
        }
        __syncthreads();
    }

    // ---- layer 2: out = relu(h+b1) @ W2 + b2, two 64-col halves ----
    float acc2[2][4];
#pragma unroll
    for (int nt = 0; nt < 2; nt++)
#pragma unroll
        for (int e = 0; e < 4; e++) acc2[nt][e] = 0.f;

    const float* W2c = g_w2t + (size_t)c * HID * 16;

    for (int half = 0; half < 2; half++) {
        __syncthreads();
        if (wn == half) {
#pragma unroll
            for (int mt = 0; mt < 2; mt++) {
#pragma unroll
                for (int nt = 0; nt < 8; nt++) {
                    int r    = wm * 32 + mt * 16 + gq;
                    int colb = nt * 8 + 2 * tg;
                    int gc   = half * 64 + colb;
                    float v0 = fmaxf(acc[mt][nt][0] + s_b1[gc],     0.f);
                    float v1 = fmaxf(acc[mt][nt][1] + s_b1[gc + 1], 0.f);
                    float v2 = fmaxf(acc[mt][nt][2] + s_b1[gc],     0.f);
                    float v3 = fmaxf(acc[mt][nt][3] + s_b1[gc + 1], 0.f);
                    S_H[r * SH_STRIDE + colb]           = __uint_as_float(f2tf32(v0));
                    S_H[r * SH_STRIDE + colb + 1]       = __uint_as_float(f2tf32(v1));
                    S_H[(r + 8) * SH_STRIDE + colb]     = __uint_as_float(f2tf32(v2));
                    S_H[(r + 8) * SH_STRIDE + colb + 1] = __uint_as_float(f2tf32(v3));
                }
            }
        }
        // stage W2 half (already tf32-rounded, n padded to 16 in gmem)
        for (int idx = tid; idx < 64 * 16; idx += 256) {
            int k = idx >> 4;
            int n = idx & 15;
            s_w2[k * SW2_STRIDE + n] = W2c[(half * 64 + k) * 16 + n];
        }
        __syncthreads();

        int r0 = warp * 16 + gq;
#pragma unroll
        for (int kk = 0; kk < 8; kk++) {
            uint32_t af[4];
            int base = r0 * SH_STRIDE + kk * 8 + tg;
            af[0] = __float_as_uint(S_H[base]);
            af[1] = __float_as_uint(S_H[base + 8 * SH_STRIDE]);
            af[2] = __float_as_uint(S_H[base + 4]);
            af[3] = __float_as_uint(S_H[base + 8 * SH_STRIDE + 4]);
            int kb = kk * 8 + tg;
#pragma unroll
            for (int nt = 0; nt < 2; nt++) {
                uint32_t bf[2];
                bf[0] = __float_as_uint(s_w2[kb * SW2_STRIDE + nt * 8 + gq]);
                bf[1] = __float_as_uint(s_w2[(kb + 4) * SW2_STRIDE + nt * 8 + gq]);
                mma_tf32(acc2[nt], af, bf);
            }
        }
    }

    // ---- store ----
#pragma unroll
    for (int nt = 0; nt < 2; nt++) {
#pragma unroll
        for (int e = 0; e < 4; e++) {
            int row = warp * 16 + gq + (e >> 1) * 8;
            int col = nt * 8 + 2 * tg + (e & 1);
            if (row < nrows && col < OUT_DIM) {
                int g = s_perm[row];
                out[(size_t)g * OUT_DIM + col] = acc2[nt][e] + s_b2[col];
            }
        }
    }
}

// ---------------- launch ----------------
extern "C" void kernel_launch(void* const* d_in, const int* in_sizes, int n_in,
                              void* d_out, int out_size) {
    const float* x   = (const float*)d_in[0];
    const int*   cam = (const int*)d_in[1];
    const float* W1  = (const float*)d_in[2];
    const float* b1  = (const float*)d_in[3];
    const float* W2  = (const float*)d_in[4];
    const float* b2  = (const float*)d_in[5];
    float* out = (float*)d_out;

    cudaFuncSetAttribute(mlp_kernel, cudaFuncAttributeMaxDynamicSharedMemorySize, SMEM_BYTES);

    wconv_kernel<<<132, 256>>>(W1, W2);
    hist_kernel<<<NHB, 256>>>(cam);
    scan_kernel<<<1, NHB>>>();
    scatter_kernel<<<NHB, 256>>>(cam);
    mlp_kernel<<<MAX_TILES, 256, SMEM_BYTES>>>(x, b1, b2, out);
}